// round 1
// baseline (speedup 1.0000x reference)
#include <cuda_runtime.h>

// ---------------- problem constants ----------------
static const int cN0 = 32768;
static const int cN1 = 8192;
static const int cN2 = 2048;
static const int cDEG = 8;
static const int cE0 = cN0 * cDEG;
static const int cE1 = cN1 * cDEG;
static const int cE2 = cN2 * cDEG;
#define MAXDEG 96

// ---------------- device scratch (static, no allocation) ----------------
__device__ float g_xA[cN0 * 96];
__device__ float g_xB[cN0 * 96];
__device__ float g_x0s[cN0 * 96];
__device__ float g_x1s[cN1 * 96];
__device__ float g_kt[cN0 * 96];
__device__ float g_vb[cN0 * 96];
__device__ float g_sb[cN0 * 96];
__device__ float g_pos1[cN1 * 3];
__device__ float g_pos2[cN2 * 3];
__device__ float g_rel0[cE0 * 3];
__device__ float g_r0[cE0];
__device__ float g_rel1[cE1 * 3];
__device__ float g_r1[cE1];
__device__ float g_rel2[cE2 * 3];
__device__ float g_r2[cE2];
__device__ float g_G[32 * 32];
__device__ int g_rp0[cN0 + 1];
__device__ int g_ei0[cE0];
__device__ int g_rp1[cN1 + 1];
__device__ int g_ei1[cE1];
__device__ int g_rp2[cN2 + 1];
__device__ int g_ei2[cE2];
__device__ int g_crp1[cN1 + 1];
__device__ int g_cei1[cN0];
__device__ int g_crp2[cN2 + 1];
__device__ int g_cei2[cN1];
__device__ int g_cnt[cN0];

// ---------------- small utility kernels ----------------
__global__ void k_zeroi(int* p, int n) {
    int i = blockIdx.x * blockDim.x + threadIdx.x;
    if (i < n) p[i] = 0;
}

__global__ void k_hist(const int* __restrict__ dst, int* cnt, int E) {
    int e = blockIdx.x * blockDim.x + threadIdx.x;
    if (e < E) atomicAdd(&cnt[dst[e]], 1);
}

// single-block exclusive scan (n <= 32768)
__global__ void k_scan(const int* __restrict__ cnt, int* rp, int n) {
    __shared__ int sh[1024];
    __shared__ int carry;
    int tid = threadIdx.x;
    if (tid == 0) carry = 0;
    __syncthreads();
    for (int base = 0; base < n; base += 1024) {
        int i = base + tid;
        int v = (i < n) ? cnt[i] : 0;
        sh[tid] = v;
        __syncthreads();
        for (int off = 1; off < 1024; off <<= 1) {
            int t = 0;
            if (tid >= off) t = sh[tid - off];
            __syncthreads();
            if (tid >= off) sh[tid] += t;
            __syncthreads();
        }
        if (i < n) rp[i + 1] = carry + sh[tid];
        __syncthreads();
        if (tid == 1023) carry += sh[1023];
        __syncthreads();
    }
    if (tid == 0) rp[0] = 0;
}

__global__ void k_scatter(const int* __restrict__ dst, const int* __restrict__ rp,
                          int* cnt, int* ei, int E) {
    int e = blockIdx.x * blockDim.x + threadIdx.x;
    if (e >= E) return;
    int d = dst[e];
    int p = rp[d] + atomicAdd(&cnt[d], 1);
    ei[p] = e;
}

// deterministic order: sort each segment ascending (tiny segments)
__global__ void k_sortseg(const int* __restrict__ rp, int* ei, int n) {
    int node = blockIdx.x * blockDim.x + threadIdx.x;
    if (node >= n) return;
    int b = rp[node], en = rp[node + 1];
    for (int i = b + 1; i < en; i++) {
        int v = ei[i];
        int j = i - 1;
        while (j >= b && ei[j] > v) { ei[j + 1] = ei[j]; j--; }
        ei[j + 1] = v;
    }
}

__global__ void k_gatherpos(float* outp, const float* __restrict__ pos,
                            const int* __restrict__ idx, int n) {
    int i = blockIdx.x * blockDim.x + threadIdx.x;
    if (i >= n * 3) return;
    int node = i / 3, k = i % 3;
    outp[i] = pos[idx[node] * 3 + k];
}

__global__ void k_edgegeo(const float* __restrict__ pos, const int* __restrict__ src,
                          const int* __restrict__ dst, float* rel, float* r, int E) {
    int e = blockIdx.x * blockDim.x + threadIdx.x;
    if (e >= E) return;
    int s = src[e], d = dst[e];
    float a = pos[d * 3 + 0] - pos[s * 3 + 0];
    float b = pos[d * 3 + 1] - pos[s * 3 + 1];
    float c = pos[d * 3 + 2] - pos[s * 3 + 2];
    rel[e * 3 + 0] = a;
    rel[e * 3 + 1] = b;
    rel[e * 3 + 2] = c;
    r[e] = sqrtf(a * a + b * b + c * c + 1e-12f);
}

// G[c][o] = sum_j Wq[o][j] * Wk[c][j]   (so logit = sum_{c,v} x_dst[c,v] * (G x_src)[c,v])
__global__ void k_gram(const float* __restrict__ Wq, const float* __restrict__ Wk,
                       float* G, int Cin, int Co) {
    int idx = blockIdx.x * blockDim.x + threadIdx.x;
    if (idx >= Cin * Cin) return;
    int c = idx / Cin, o = idx % Cin;
    float s = 0.f;
    for (int j = 0; j < Co; j++) s += Wq[o * Co + j] * Wk[c * Co + j];
    G[c * Cin + o] = s;
}

// ---------------- per-layer prep: kt = G^T-mix(x), vb = x@Wv, sb = x@Ws ----------------
// layout: x [n][v][Cin], kt [n][v][Cin], vb/sb [n][v][Co]
template <int Cin, int Co>
__global__ void k_prep(const float* __restrict__ x, const float* __restrict__ G,
                       const float* __restrict__ Wv, const float* __restrict__ Ws,
                       float* __restrict__ kt, float* __restrict__ vb,
                       float* __restrict__ sb, int n) {
    __shared__ float sA[Cin * Cin];
    __shared__ float sWv[Cin * Co];
    __shared__ float sWs[Cin * Co];
    __shared__ float sx[8][3 * Cin];
    int tid = threadIdx.x;
    for (int i = tid; i < Cin * Cin; i += 256) sA[i] = G[i];
    for (int i = tid; i < Cin * Co; i += 256) { sWv[i] = Wv[i]; sWs[i] = Ws[i]; }
    __syncthreads();
    int warp = tid >> 5, lane = tid & 31;
    for (int node = blockIdx.x * 8 + warp; node < n; node += gridDim.x * 8) {
        for (int i = lane; i < 3 * Cin; i += 32) sx[warp][i] = x[node * 3 * Cin + i];
        __syncwarp();
        float akt0 = 0, akt1 = 0, akt2 = 0;
        float av0 = 0, av1 = 0, av2 = 0;
        float as0 = 0, as1 = 0, as2 = 0;
#pragma unroll
        for (int c = 0; c < Cin; c++) {
            float x0 = sx[warp][0 * Cin + c];
            float x1 = sx[warp][1 * Cin + c];
            float x2 = sx[warp][2 * Cin + c];
            if (lane < Cin) {
                float a = sA[c * Cin + lane];
                akt0 += x0 * a; akt1 += x1 * a; akt2 += x2 * a;
            }
            if (lane < Co) {
                float wv = sWv[c * Co + lane];
                float ws = sWs[c * Co + lane];
                av0 += x0 * wv; av1 += x1 * wv; av2 += x2 * wv;
                as0 += x0 * ws; as1 += x1 * ws; as2 += x2 * ws;
            }
        }
        if (lane < Cin) {
            float* kp = kt + node * 3 * Cin + lane;
            kp[0] = akt0; kp[Cin] = akt1; kp[2 * Cin] = akt2;
        }
        if (lane < Co) {
            float* vp = vb + node * 3 * Co + lane;
            vp[0] = av0; vp[Co] = av1; vp[2 * Co] = av2;
            float* sp = sb + node * 3 * Co + lane;
            sp[0] = as0; sp[Co] = as1; sp[2 * Co] = as2;
        }
        __syncwarp();
    }
}

// ---------------- attention + norm_bias, one warp per destination node ----------------
template <int Cin, int Co>
__global__ void k_attn(const float* __restrict__ x, const float* __restrict__ kt,
                       const float* __restrict__ vb, const float* __restrict__ sb,
                       const int* __restrict__ rp, const int* __restrict__ ei,
                       const int* __restrict__ src, const float* __restrict__ rel,
                       const float* __restrict__ r, const float* __restrict__ w1,
                       const float* __restrict__ w2, const float* __restrict__ scale,
                       const float* __restrict__ bias, float* __restrict__ outp,
                       int n, float scl) {
    __shared__ float sh[8][MAXDEG];
    int warp = threadIdx.x >> 5, lane = threadIdx.x & 31;
    float rw1 = (lane < 16) ? w1[lane] : 0.f;
    float rw2 = (lane < 16) ? w2[lane] : 0.f;
    float sc_o = (lane < Co) ? scale[lane] : 0.f;
    float bi_o = (lane < Co) ? bias[lane] : 0.f;
    for (int node = blockIdx.x * 8 + warp; node < n; node += gridDim.x * 8) {
        int e0 = rp[node];
        int deg = rp[node + 1] - e0;
        if (deg > MAXDEG) deg = MAXDEG;
        float xd0 = 0, xd1 = 0, xd2 = 0;
        if (lane < Cin) {
            const float* xp = x + node * 3 * Cin + lane;
            xd0 = xp[0]; xd1 = xp[Cin]; xd2 = xp[2 * Cin];
        }
        // pass 1: logits
        for (int j = 0; j < deg; j++) {
            int e = ei[e0 + j];
            int s = src[e];
            float part = 0.f;
            if (lane < Cin) {
                const float* kp = kt + s * 3 * Cin + lane;
                part = xd0 * kp[0] + xd1 * kp[Cin] + xd2 * kp[2 * Cin];
            }
            part *= scl;
            float rr = r[e];
            if (lane < 16) part += fmaxf(rr * rw1, 0.f) * rw2;
#pragma unroll
            for (int off = 16; off; off >>= 1) part += __shfl_xor_sync(0xffffffffu, part, off);
            if (lane == 0) sh[warp][j] = part;
        }
        __syncwarp();
        // softmax
        float m = -1e30f;
        for (int j = lane; j < deg; j += 32) m = fmaxf(m, sh[warp][j]);
#pragma unroll
        for (int off = 16; off; off >>= 1) m = fmaxf(m, __shfl_xor_sync(0xffffffffu, m, off));
        float z = 0.f;
        for (int j = lane; j < deg; j += 32) {
            float ex = __expf(sh[warp][j] - m);
            sh[warp][j] = ex;
            z += ex;
        }
#pragma unroll
        for (int off = 16; off; off >>= 1) z += __shfl_xor_sync(0xffffffffu, z, off);
        float invz = 1.f / (z + 1e-9f);
        __syncwarp();
        // pass 2: aggregate + skip + norm_bias
        if (lane < Co) {
            float a0 = 0, a1 = 0, a2 = 0;
            for (int j = 0; j < deg; j++) {
                int e = ei[e0 + j];
                int s = src[e];
                float al = sh[warp][j] * invz;
                const float* vp = vb + s * 3 * Co + lane;
                const float* rr3 = rel + e * 3;
                a0 += al * (vp[0] + rr3[0]);
                a1 += al * (vp[Co] + rr3[1]);
                a2 += al * (vp[2 * Co] + rr3[2]);
            }
            const float* sp = sb + node * 3 * Co + lane;
            a0 += sp[0]; a1 += sp[Co]; a2 += sp[2 * Co];
            float nrm = sqrtf(a0 * a0 + a1 * a1 + a2 * a2 + 1e-12f);
            float t = sc_o * nrm + bi_o;
            t = t > 0.f ? t : 0.f;
            float f = t / nrm;
            float* op = outp + node * 3 * Co + lane;
            op[0] = a0 * f; op[Co] = a1 * f; op[2 * Co] = a2 * f;
        }
        __syncwarp();
    }
}

// ---------------- pooling (segment mean, deterministic via CSR) ----------------
__global__ void k_segmean(const float* __restrict__ xin, const int* __restrict__ rp,
                          const int* __restrict__ ci, float* __restrict__ outp, int nseg) {
    int warp = (blockIdx.x * blockDim.x + threadIdx.x) >> 5;
    int lane = threadIdx.x & 31;
    if (warp >= nseg) return;
    int b = rp[warp];
    int deg = rp[warp + 1] - b;
    float a0 = 0, a1 = 0, a2 = 0;
    for (int j = 0; j < deg; j++) {
        int mnode = ci[b + j];
        const float* xp = xin + mnode * 96 + lane;
        a0 += xp[0]; a1 += xp[32]; a2 += xp[64];
    }
    float inv = 1.f / ((float)deg + 1e-9f);
    float* op = outp + warp * 96 + lane;
    op[0] = a0 * inv; op[32] = a1 * inv; op[64] = a2 * inv;
}

// scatter-add upsample (fp indices are distinct -> no atomics)
__global__ void k_scatadd(float* outp, const int* __restrict__ fp,
                          const float* __restrict__ xin, int nidx) {
    int i = blockIdx.x * blockDim.x + threadIdx.x;
    if (i >= nidx * 96) return;
    int node = i / 96, t = i % 96;
    outp[fp[node] * 96 + t] += xin[i];
}

// final MLP head: out[n][o] = relu(sum_f x[n][f] * W[f][o]), OUT=40
__global__ void k_mlp(const float* __restrict__ xin, const float* __restrict__ W,
                      float* __restrict__ outp, int n) {
    int i = blockIdx.x * blockDim.x + threadIdx.x;
    if (i >= n * 40) return;
    int node = i / 40, o = i % 40;
    float s = xin[node * 3 + 0] * W[o] + xin[node * 3 + 1] * W[40 + o] +
              xin[node * 3 + 2] * W[80 + o];
    outp[i] = s > 0.f ? s : 0.f;
}

// ---------------- host orchestration ----------------
#define GETSYM(p, s)                              \
    do {                                          \
        void* _t;                                 \
        cudaGetSymbolAddress(&_t, s);             \
        p = (decltype(p))_t;                      \
    } while (0)

static void build_csr(const int* dst, int E, int n, int* rp, int* ei, int* cnt) {
    k_zeroi<<<(n + 255) / 256, 256>>>(cnt, n);
    k_hist<<<(E + 255) / 256, 256>>>(dst, cnt, E);
    k_scan<<<1, 1024>>>(cnt, rp, n);
    k_zeroi<<<(n + 255) / 256, 256>>>(cnt, n);
    k_scatter<<<(E + 255) / 256, 256>>>(dst, rp, cnt, ei, E);
    k_sortseg<<<(n + 255) / 256, 256>>>(rp, ei, n);
}

extern "C" void kernel_launch(void* const* d_in, const int* in_sizes, int n_in,
                              void* d_out, int out_size) {
    const float* pos0 = (const float*)d_in[0];
    const float* v0 = (const float*)d_in[1];
    const float* Wq_first = (const float*)d_in[2];
    const float* Wk_first = (const float*)d_in[3];
    const float* Wv_first = (const float*)d_in[4];
    const float* Ws_first = (const float*)d_in[5];
    const float* Wq_mid = (const float*)d_in[6];
    const float* Wk_mid = (const float*)d_in[7];
    const float* Wv_mid = (const float*)d_in[8];
    const float* Ws_mid = (const float*)d_in[9];
    const float* Wq_last = (const float*)d_in[10];
    const float* Wk_last = (const float*)d_in[11];
    const float* Wv_last = (const float*)d_in[12];
    const float* Ws_last = (const float*)d_in[13];
    const float* wr1 = (const float*)d_in[14];
    const float* wr2 = (const float*)d_in[15];
    const float* scale_mid = (const float*)d_in[16];
    const float* bias_mid = (const float*)d_in[17];
    const float* scale_last = (const float*)d_in[18];
    const float* bias_last = (const float*)d_in[19];
    const float* Wmlp = (const float*)d_in[20];
    const int* src0 = (const int*)d_in[21];
    const int* dst0 = (const int*)d_in[22];
    const int* src1 = (const int*)d_in[23];
    const int* dst1 = (const int*)d_in[24];
    const int* src2 = (const int*)d_in[25];
    const int* dst2 = (const int*)d_in[26];
    const int* fp1 = (const int*)d_in[27];
    const int* fp2 = (const int*)d_in[28];
    const int* cl1 = (const int*)d_in[29];
    const int* cl2 = (const int*)d_in[30];
    float* outp = (float*)d_out;

    float *xA, *xB, *x0s, *x1s, *kt, *vb, *sb, *pos1, *pos2;
    float *rel0, *r0, *rel1, *r1, *rel2, *r2, *G;
    int *rp0, *ei0, *rp1, *ei1, *rp2, *ei2, *crp1, *cei1, *crp2, *cei2, *cnt;
    GETSYM(xA, g_xA); GETSYM(xB, g_xB); GETSYM(x0s, g_x0s); GETSYM(x1s, g_x1s);
    GETSYM(kt, g_kt); GETSYM(vb, g_vb); GETSYM(sb, g_sb);
    GETSYM(pos1, g_pos1); GETSYM(pos2, g_pos2);
    GETSYM(rel0, g_rel0); GETSYM(r0, g_r0);
    GETSYM(rel1, g_rel1); GETSYM(r1, g_r1);
    GETSYM(rel2, g_rel2); GETSYM(r2, g_r2);
    GETSYM(G, g_G);
    GETSYM(rp0, g_rp0); GETSYM(ei0, g_ei0);
    GETSYM(rp1, g_rp1); GETSYM(ei1, g_ei1);
    GETSYM(rp2, g_rp2); GETSYM(ei2, g_ei2);
    GETSYM(crp1, g_crp1); GETSYM(cei1, g_cei1);
    GETSYM(crp2, g_crp2); GETSYM(cei2, g_cei2);
    GETSYM(cnt, g_cnt);

    // geometry
    k_gatherpos<<<(cN1 * 3 + 255) / 256, 256>>>(pos1, pos0, fp1, cN1);
    k_gatherpos<<<(cN2 * 3 + 255) / 256, 256>>>(pos2, pos1, fp2, cN2);
    k_edgegeo<<<(cE0 + 255) / 256, 256>>>(pos0, src0, dst0, rel0, r0, cE0);
    k_edgegeo<<<(cE1 + 255) / 256, 256>>>(pos1, src1, dst1, rel1, r1, cE1);
    k_edgegeo<<<(cE2 + 255) / 256, 256>>>(pos2, src2, dst2, rel2, r2, cE2);

    // CSR structures (edges per level + cluster membership)
    build_csr(dst0, cE0, cN0, rp0, ei0, cnt);
    build_csr(dst1, cE1, cN1, rp1, ei1, cnt);
    build_csr(dst2, cE2, cN2, rp2, ei2, cnt);
    build_csr(cl1, cN0, cN1, crp1, cei1, cnt);
    build_csr(cl2, cN1, cN2, crp2, cei2, cnt);

    const float scl_mid = 0.10206207261596575f;  // 1/sqrt(96)
    const float scl_last = 0.5773502691896258f;  // 1/sqrt(3)

    struct LayerDesc {
        int n;
        const int *rp, *ei, *src;
        const float *rel, *r;
        const float *Wq, *Wk, *Wv, *Ws;
        const float *sc, *bi, *w1, *w2;
        const float* xin;
        float* xout;
        int Cin, Co;
        float scl;
    };

    // layer weight slices
    auto midW = [&](const float* base, int i) { return base + i * 32 * 32; };

    LayerDesc L[10];
    // layer 0: level 0, 1->32
    L[0] = {cN0, rp0, ei0, src0, rel0, r0, Wq_first, Wk_first, Wv_first, Ws_first,
            scale_mid + 0, bias_mid + 0, wr1 + 0, wr2 + 0, v0, xA, 1, 32, scl_mid};
    // layer 1: level 0, 32->32, output saved as x0
    L[1] = {cN0, rp0, ei0, src0, rel0, r0, midW(Wq_mid, 0), midW(Wk_mid, 0),
            midW(Wv_mid, 0), midW(Ws_mid, 0), scale_mid + 32, bias_mid + 32,
            wr1 + 16, wr2 + 16, xA, x0s, 32, 32, scl_mid};
    // layers 2,3: level 1
    L[2] = {cN1, rp1, ei1, src1, rel1, r1, midW(Wq_mid, 1), midW(Wk_mid, 1),
            midW(Wv_mid, 1), midW(Ws_mid, 1), scale_mid + 64, bias_mid + 64,
            wr1 + 32, wr2 + 32, xA, xB, 32, 32, scl_mid};
    L[3] = {cN1, rp1, ei1, src1, rel1, r1, midW(Wq_mid, 2), midW(Wk_mid, 2),
            midW(Wv_mid, 2), midW(Ws_mid, 2), scale_mid + 96, bias_mid + 96,
            wr1 + 48, wr2 + 48, xB, x1s, 32, 32, scl_mid};
    // layers 4,5: level 2 (bottleneck)
    L[4] = {cN2, rp2, ei2, src2, rel2, r2, midW(Wq_mid, 3), midW(Wk_mid, 3),
            midW(Wv_mid, 3), midW(Ws_mid, 3), scale_mid + 128, bias_mid + 128,
            wr1 + 64, wr2 + 64, xA, xB, 32, 32, scl_mid};
    L[5] = {cN2, rp2, ei2, src2, rel2, r2, midW(Wq_mid, 4), midW(Wk_mid, 4),
            midW(Wv_mid, 4), midW(Ws_mid, 4), scale_mid + 160, bias_mid + 160,
            wr1 + 80, wr2 + 80, xB, xA, 32, 32, scl_mid};
    // layers 6,7: level 1 (up)
    L[6] = {cN1, rp1, ei1, src1, rel1, r1, midW(Wq_mid, 5), midW(Wk_mid, 5),
            midW(Wv_mid, 5), midW(Ws_mid, 5), scale_mid + 192, bias_mid + 192,
            wr1 + 96, wr2 + 96, xB, xA, 32, 32, scl_mid};
    L[7] = {cN1, rp1, ei1, src1, rel1, r1, midW(Wq_mid, 6), midW(Wk_mid, 6),
            midW(Wv_mid, 6), midW(Ws_mid, 6), scale_mid + 224, bias_mid + 224,
            wr1 + 112, wr2 + 112, xA, xB, 32, 32, scl_mid};
    // layers 8,9: level 0 (up)
    L[8] = {cN0, rp0, ei0, src0, rel0, r0, midW(Wq_mid, 7), midW(Wk_mid, 7),
            midW(Wv_mid, 7), midW(Ws_mid, 7), scale_mid + 256, bias_mid + 256,
            wr1 + 128, wr2 + 128, xA, xB, 32, 32, scl_mid};
    L[9] = {cN0, rp0, ei0, src0, rel0, r0, Wq_last, Wk_last, Wv_last, Ws_last,
            scale_last, bias_last, wr1 + 144, wr2 + 144, xB, xA, 32, 1, scl_last};

    auto run_layer = [&](const LayerDesc& d) {
        k_gram<<<(d.Cin * d.Cin + 255) / 256, 256>>>(d.Wq, d.Wk, G, d.Cin, d.Co);
        int blocks = (d.n + 7) / 8;
        if (d.Cin == 1) {
            k_prep<1, 32><<<blocks, 256>>>(d.xin, G, d.Wv, d.Ws, kt, vb, sb, d.n);
            k_attn<1, 32><<<blocks, 256>>>(d.xin, kt, vb, sb, d.rp, d.ei, d.src, d.rel,
                                           d.r, d.w1, d.w2, d.sc, d.bi, d.xout, d.n, d.scl);
        } else if (d.Co == 32) {
            k_prep<32, 32><<<blocks, 256>>>(d.xin, G, d.Wv, d.Ws, kt, vb, sb, d.n);
            k_attn<32, 32><<<blocks, 256>>>(d.xin, kt, vb, sb, d.rp, d.ei, d.src, d.rel,
                                            d.r, d.w1, d.w2, d.sc, d.bi, d.xout, d.n, d.scl);
        } else {
            k_prep<32, 1><<<blocks, 256>>>(d.xin, G, d.Wv, d.Ws, kt, vb, sb, d.n);
            k_attn<32, 1><<<blocks, 256>>>(d.xin, kt, vb, sb, d.rp, d.ei, d.src, d.rel,
                                           d.r, d.w1, d.w2, d.sc, d.bi, d.xout, d.n, d.scl);
        }
    };

    // ---- down block 0 (level 0) ----
    run_layer(L[0]);
    run_layer(L[1]);  // -> x0s
    // pool -> level 1
    k_segmean<<<(cN1 + 7) / 8, 256>>>(x0s, crp1, cei1, xA, cN1);
    run_layer(L[2]);
    run_layer(L[3]);  // -> x1s
    // pool -> level 2
    k_segmean<<<(cN2 + 7) / 8, 256>>>(x1s, crp2, cei2, xA, cN2);
    run_layer(L[4]);
    run_layer(L[5]);  // -> xA (bottleneck out, N2)
    // upsample to level 1: xB = x1s; xB[fp2] += xA
    cudaMemcpyAsync(xB, x1s, (size_t)cN1 * 96 * sizeof(float), cudaMemcpyDeviceToDevice, 0);
    k_scatadd<<<(cN2 * 96 + 255) / 256, 256>>>(xB, fp2, xA, cN2);
    run_layer(L[6]);
    run_layer(L[7]);  // -> xB (N1)
    // upsample to level 0: xA = x0s; xA[fp1] += xB
    cudaMemcpyAsync(xA, x0s, (size_t)cN0 * 96 * sizeof(float), cudaMemcpyDeviceToDevice, 0);
    k_scatadd<<<(cN1 * 96 + 255) / 256, 256>>>(xA, fp1, xB, cN1);
    run_layer(L[8]);
    run_layer(L[9]);  // -> xA ([N0,3])
    // final MLP head
    k_mlp<<<(cN0 * 40 + 255) / 256, 256>>>(xA, Wmlp, outp, cN0);
}

// round 3
// speedup vs baseline: 1.2636x; 1.2636x over previous
#include <cuda_runtime.h>

typedef unsigned long long u64;

// ---------------- problem constants ----------------
static const int N0n = 32768;
static const int N1n = 8192;
static const int N2n = 2048;
static const int E0n = N0n * 8;
static const int E1n = N1n * 8;
static const int E2n = N2n * 8;
#define SLOTE 64
#define SLOTC 48

// ---------------- device scratch (static, no allocation) ----------------
__device__ float g_xA[N0n * 96];
__device__ float g_xB[N0n * 96];
__device__ float g_x0s[N0n * 96];
__device__ float g_x1s[N1n * 96];
__device__ float g_kt[N0n * 96];
__device__ float g_vb[N0n * 96];
__device__ float g_sb[N0n * 96];
__device__ float g_pos1[N1n * 3];
__device__ float g_pos2[N2n * 3];
__device__ float g_rel0[E0n * 3];
__device__ float g_r0[E0n];
__device__ float g_rel1[E1n * 3];
__device__ float g_r1[E1n];
__device__ float g_rel2[E2n * 3];
__device__ float g_r2[E2n];
__device__ int g_cnts[N0n + N1n + N2n + N1n + N2n];
__device__ int g_esl0[N0n * SLOTE];
__device__ int g_esl1[N1n * SLOTE];
__device__ int g_esl2[N2n * SLOTE];
__device__ int g_csl1[N1n * SLOTC];
__device__ int g_csl2[N2n * SLOTC];
__device__ int g_gS0[N0n * SLOTE];
__device__ float g_gR0[N0n * SLOTE];
__device__ float g_gRel0[N0n * SLOTE * 3];
__device__ int g_gS1[N1n * SLOTE];
__device__ float g_gR1[N1n * SLOTE];
__device__ float g_gRel1[N1n * SLOTE * 3];
__device__ int g_gS2[N2n * SLOTE];
__device__ float g_gR2[N2n * SLOTE];
__device__ float g_gRel2[N2n * SLOTE * 3];

// ---------------- f32x2 helpers ----------------
__device__ __forceinline__ u64 pack2(float a, float b) {
    u64 r;
    asm("mov.b64 %0,{%1,%2};" : "=l"(r) : "f"(a), "f"(b));
    return r;
}
__device__ __forceinline__ void fma2(u64& d, u64 a, u64 b) {
    asm("fma.rn.f32x2 %0,%1,%2,%0;" : "+l"(d) : "l"(a), "l"(b));
}
__device__ __forceinline__ float2 unp(u64 v) {
    float2 t;
    asm("mov.b64 {%0,%1},%2;" : "=f"(t.x), "=f"(t.y) : "l"(v));
    return t;
}

// ---------------- utility kernels ----------------
__global__ void k_zeroi(int* p, int n) {
    int i = blockIdx.x * blockDim.x + threadIdx.x;
    if (i < n) p[i] = 0;
}

__global__ void k_scat(const int* __restrict__ key, int* cnt, int* slot, int nk, int stride) {
    int e = blockIdx.x * blockDim.x + threadIdx.x;
    if (e >= nk) return;
    int k = key[e];
    int p = atomicAdd(&cnt[k], 1);
    if (p < stride) slot[k * stride + p] = e;
}

__global__ void k_finedge(const int* __restrict__ cnt, int* slot, const int* __restrict__ src,
                          const float* __restrict__ rel, const float* __restrict__ r,
                          int* __restrict__ gS, float* __restrict__ gR,
                          float* __restrict__ gRel, int n) {
    int node = blockIdx.x * blockDim.x + threadIdx.x;
    if (node >= n) return;
    int deg = min(cnt[node], SLOTE);
    int base = node * SLOTE;
    for (int i = 1; i < deg; i++) {
        int v = slot[base + i];
        int j = i - 1;
        while (j >= 0 && slot[base + j] > v) { slot[base + j + 1] = slot[base + j]; j--; }
        slot[base + j + 1] = v;
    }
    for (int j = 0; j < deg; j++) {
        int e = slot[base + j];
        gS[base + j] = src[e];
        gR[base + j] = r[e];
        gRel[(base + j) * 3 + 0] = rel[e * 3 + 0];
        gRel[(base + j) * 3 + 1] = rel[e * 3 + 1];
        gRel[(base + j) * 3 + 2] = rel[e * 3 + 2];
    }
}

__global__ void k_sortc(const int* __restrict__ cnt, int* slot, int n) {
    int node = blockIdx.x * blockDim.x + threadIdx.x;
    if (node >= n) return;
    int deg = min(cnt[node], SLOTC);
    int base = node * SLOTC;
    for (int i = 1; i < deg; i++) {
        int v = slot[base + i];
        int j = i - 1;
        while (j >= 0 && slot[base + j] > v) { slot[base + j + 1] = slot[base + j]; j--; }
        slot[base + j + 1] = v;
    }
}

__global__ void k_gatherpos(float* outp, const float* __restrict__ pos,
                            const int* __restrict__ idx, int n) {
    int i = blockIdx.x * blockDim.x + threadIdx.x;
    if (i >= n * 3) return;
    int node = i / 3, k = i % 3;
    outp[i] = pos[idx[node] * 3 + k];
}

__global__ void k_edgegeo(const float* __restrict__ pos, const int* __restrict__ src,
                          const int* __restrict__ dst, float* rel, float* r, int E) {
    int e = blockIdx.x * blockDim.x + threadIdx.x;
    if (e >= E) return;
    int s = src[e], d = dst[e];
    float a = pos[d * 3 + 0] - pos[s * 3 + 0];
    float b = pos[d * 3 + 1] - pos[s * 3 + 1];
    float c = pos[d * 3 + 2] - pos[s * 3 + 2];
    rel[e * 3 + 0] = a;
    rel[e * 3 + 1] = b;
    rel[e * 3 + 2] = c;
    r[e] = sqrtf(a * a + b * b + c * c + 1e-12f);
}

// ---------------- prep, Cin=1 (first layer) ----------------
__global__ __launch_bounds__(256) void k_prep1(const float* __restrict__ x,
                                               const float* __restrict__ Wq,
                                               const float* __restrict__ Wk,
                                               const float* __restrict__ Wv,
                                               const float* __restrict__ Ws,
                                               float* __restrict__ kt, float* __restrict__ vb,
                                               float* __restrict__ sb, int n) {
    const int Co = 32;
    int tid = threadIdx.x;
    int warp = tid >> 5, lane = tid & 31;
    __shared__ float sG;
    __shared__ float sWvs[Co], sWss[Co];
    if (tid == 0) {
        float s = 0.f;
        for (int j = 0; j < Co; j++) s += Wq[j] * Wk[j];
        sG = s;
    }
    if (tid < Co) { sWvs[tid] = Wv[tid]; sWss[tid] = Ws[tid]; }
    __syncthreads();
    float G = sG;
    for (int node = blockIdx.x * 8 + warp; node < n; node += gridDim.x * 8) {
        float x0 = x[node * 3 + 0], x1 = x[node * 3 + 1], x2 = x[node * 3 + 2];
        if (lane == 0) {
            kt[node * 3 + 0] = G * x0;
            kt[node * 3 + 1] = G * x1;
            kt[node * 3 + 2] = G * x2;
        }
        float wv = sWvs[lane], ws = sWss[lane];
        float* vp = vb + node * 3 * Co + lane;
        vp[0] = x0 * wv; vp[Co] = x1 * wv; vp[2 * Co] = x2 * wv;
        float* sp = sb + node * 3 * Co + lane;
        sp[0] = x0 * ws; sp[Co] = x1 * ws; sp[2 * Co] = x2 * ws;
    }
}

// ---------------- prep, Cin=32 (gram fused, f32x2 packed) ----------------
template <int Co>
__global__ __launch_bounds__(256) void k_prep32(const float* __restrict__ x,
                                                const float* __restrict__ Wq,
                                                const float* __restrict__ Wk,
                                                const float* __restrict__ Wv,
                                                const float* __restrict__ Ws,
                                                float* __restrict__ kt, float* __restrict__ vb,
                                                float* __restrict__ sb, int n) {
    const int Cin = 32;
    const int H = Cin / 2;  // 16
    int tid = threadIdx.x;
    int warp = tid >> 5, lane = tid & 31;
    __shared__ u64 sGp[H * Cin];
    __shared__ u64 sWvp[H * Co];
    __shared__ u64 sWsp[H * Co];
    __shared__ u64 sxp[8][3 * H];
    for (int i = tid; i < H * Cin; i += 256) {
        int c2 = i / Cin, o = i % Cin;
        float g0 = 0.f, g1 = 0.f;
        for (int j = 0; j < Co; j++) {
            float wq = Wq[o * Co + j];
            g0 += wq * Wk[(2 * c2) * Co + j];
            g1 += wq * Wk[(2 * c2 + 1) * Co + j];
        }
        sGp[i] = pack2(g0, g1);
    }
    for (int i = tid; i < H * Co; i += 256) {
        int c2 = i / Co, o = i % Co;
        sWvp[i] = pack2(Wv[(2 * c2) * Co + o], Wv[(2 * c2 + 1) * Co + o]);
        sWsp[i] = pack2(Ws[(2 * c2) * Co + o], Ws[(2 * c2 + 1) * Co + o]);
    }
    __syncthreads();
    for (int node = blockIdx.x * 8 + warp; node < n; node += gridDim.x * 8) {
        const float2* xr = (const float2*)(x + node * 3 * Cin);
        for (int i = lane; i < 3 * H; i += 32) {
            float2 t = xr[i];
            sxp[warp][i] = pack2(t.x, t.y);
        }
        __syncwarp();
        u64 k0 = 0, k1 = 0, k2 = 0, v0a = 0, v1a = 0, v2a = 0, s0a = 0, s1a = 0, s2a = 0;
#pragma unroll
        for (int c2 = 0; c2 < H; c2++) {
            u64 px0 = sxp[warp][c2];
            u64 px1 = sxp[warp][H + c2];
            u64 px2 = sxp[warp][2 * H + c2];
            {
                u64 g = sGp[c2 * Cin + lane];
                fma2(k0, px0, g); fma2(k1, px1, g); fma2(k2, px2, g);
            }
            if (Co == 32 || lane < Co) {
                int li = (Co == 32) ? lane : 0;
                u64 wv = sWvp[c2 * Co + li];
                u64 ws = sWsp[c2 * Co + li];
                fma2(v0a, px0, wv); fma2(v1a, px1, wv); fma2(v2a, px2, wv);
                fma2(s0a, px0, ws); fma2(s1a, px1, ws); fma2(s2a, px2, ws);
            }
        }
        {
            float2 a = unp(k0), b = unp(k1), c = unp(k2);
            float* kp = kt + node * 3 * Cin + lane;
            kp[0] = a.x + a.y; kp[Cin] = b.x + b.y; kp[2 * Cin] = c.x + c.y;
        }
        if (lane < Co) {
            float2 a = unp(v0a), b = unp(v1a), c = unp(v2a);
            float* vp = vb + node * 3 * Co + lane;
            vp[0] = a.x + a.y; vp[Co] = b.x + b.y; vp[2 * Co] = c.x + c.y;
            a = unp(s0a); b = unp(s1a); c = unp(s2a);
            float* sp = sb + node * 3 * Co + lane;
            sp[0] = a.x + a.y; sp[Co] = b.x + b.y; sp[2 * Co] = c.x + c.y;
        }
        __syncwarp();
    }
}

// ---------------- attention (online softmax) + norm_bias ----------------
template <int Cin, int Co>
__global__ __launch_bounds__(256) void k_attn(
    const float* __restrict__ x, const float* __restrict__ kt, const float* __restrict__ vb,
    const float* __restrict__ sb, const int* __restrict__ cnt, const int* __restrict__ gS,
    const float* __restrict__ gR, const float* __restrict__ gRel,
    const float* __restrict__ w1, const float* __restrict__ w2,
    const float* __restrict__ scale, const float* __restrict__ bias, float* __restrict__ outp,
    int n, float scl) {
    int warp = threadIdx.x >> 5, lane = threadIdx.x & 31;
    int node = blockIdx.x * 8 + warp;
    if (node >= n) return;
    float rw1 = (lane < 16) ? w1[lane] : 0.f;
    float rw2 = (lane < 16) ? w2[lane] : 0.f;
    float sc_o = (lane < Co) ? scale[lane] : 0.f;
    float bi_o = (lane < Co) ? bias[lane] : 0.f;
    int deg = min(cnt[node], SLOTE);
    int base = node * SLOTE;
    float xd0 = 0.f, xd1 = 0.f, xd2 = 0.f;
    if (lane < Cin) {
        const float* xp = x + node * 3 * Cin + lane;
        xd0 = xp[0]; xd1 = xp[Cin]; xd2 = xp[2 * Cin];
    }
    float m = -1e30f, z = 0.f, a0 = 0.f, a1 = 0.f, a2 = 0.f;
    int j = 0;
    for (; j + 2 <= deg; j += 2) {
        int s0 = gS[base + j], s1 = gS[base + j + 1];
        float re0 = gR[base + j], re1 = gR[base + j + 1];
        float p0 = 0.f, p1 = 0.f;
        float v00 = 0.f, v01 = 0.f, v02 = 0.f, v10 = 0.f, v11 = 0.f, v12 = 0.f;
        if (lane < Cin) {
            const float* kp0 = kt + s0 * 3 * Cin + lane;
            const float* kp1 = kt + s1 * 3 * Cin + lane;
            p0 = xd0 * kp0[0] + xd1 * kp0[Cin] + xd2 * kp0[2 * Cin];
            p1 = xd0 * kp1[0] + xd1 * kp1[Cin] + xd2 * kp1[2 * Cin];
        }
        if (lane < Co) {
            const float* vp0 = vb + s0 * 3 * Co + lane;
            const float* vp1 = vb + s1 * 3 * Co + lane;
            v00 = vp0[0]; v01 = vp0[Co]; v02 = vp0[2 * Co];
            v10 = vp1[0]; v11 = vp1[Co]; v12 = vp1[2 * Co];
        }
        p0 *= scl; p1 *= scl;
        if (lane < 16) {
            p0 += fmaxf(re0 * rw1, 0.f) * rw2;
            p1 += fmaxf(re1 * rw1, 0.f) * rw2;
        }
#pragma unroll
        for (int off = 16; off; off >>= 1) {
            p0 += __shfl_xor_sync(0xffffffffu, p0, off);
            p1 += __shfl_xor_sync(0xffffffffu, p1, off);
        }
        float rl0 = gRel[(base + j) * 3 + 0];
        float rl1 = gRel[(base + j) * 3 + 1];
        float rl2 = gRel[(base + j) * 3 + 2];
        float mn = fmaxf(m, p0);
        float f = __expf(m - mn);
        float w = __expf(p0 - mn);
        z = z * f + w;
        a0 = a0 * f + w * (v00 + rl0);
        a1 = a1 * f + w * (v01 + rl1);
        a2 = a2 * f + w * (v02 + rl2);
        m = mn;
        rl0 = gRel[(base + j + 1) * 3 + 0];
        rl1 = gRel[(base + j + 1) * 3 + 1];
        rl2 = gRel[(base + j + 1) * 3 + 2];
        mn = fmaxf(m, p1);
        f = __expf(m - mn);
        w = __expf(p1 - mn);
        z = z * f + w;
        a0 = a0 * f + w * (v10 + rl0);
        a1 = a1 * f + w * (v11 + rl1);
        a2 = a2 * f + w * (v12 + rl2);
        m = mn;
    }
    if (j < deg) {
        int s0 = gS[base + j];
        float re0 = gR[base + j];
        float p0 = 0.f, v00 = 0.f, v01 = 0.f, v02 = 0.f;
        if (lane < Cin) {
            const float* kp0 = kt + s0 * 3 * Cin + lane;
            p0 = xd0 * kp0[0] + xd1 * kp0[Cin] + xd2 * kp0[2 * Cin];
        }
        if (lane < Co) {
            const float* vp0 = vb + s0 * 3 * Co + lane;
            v00 = vp0[0]; v01 = vp0[Co]; v02 = vp0[2 * Co];
        }
        p0 *= scl;
        if (lane < 16) p0 += fmaxf(re0 * rw1, 0.f) * rw2;
#pragma unroll
        for (int off = 16; off; off >>= 1) p0 += __shfl_xor_sync(0xffffffffu, p0, off);
        float rl0 = gRel[(base + j) * 3 + 0];
        float rl1 = gRel[(base + j) * 3 + 1];
        float rl2 = gRel[(base + j) * 3 + 2];
        float mn = fmaxf(m, p0);
        float f = __expf(m - mn);
        float w = __expf(p0 - mn);
        z = z * f + w;
        a0 = a0 * f + w * (v00 + rl0);
        a1 = a1 * f + w * (v01 + rl1);
        a2 = a2 * f + w * (v02 + rl2);
    }
    float invz = 1.f / (z + 1e-9f);
    if (lane < Co) {
        const float* sp = sb + node * 3 * Co + lane;
        a0 = a0 * invz + sp[0];
        a1 = a1 * invz + sp[Co];
        a2 = a2 * invz + sp[2 * Co];
        float nrm = sqrtf(a0 * a0 + a1 * a1 + a2 * a2 + 1e-12f);
        float t = fmaxf(sc_o * nrm + bi_o, 0.f);
        float fct = t / nrm;
        float* op = outp + node * 3 * Co + lane;
        op[0] = a0 * fct; op[Co] = a1 * fct; op[2 * Co] = a2 * fct;
    }
}

// ---------------- pooling / upsample / head ----------------
__global__ void k_segmean(const float* __restrict__ xin, const int* __restrict__ cnt,
                          const int* __restrict__ csl, float* __restrict__ outp, int nseg) {
    int warp = (blockIdx.x * blockDim.x + threadIdx.x) >> 5;
    int lane = threadIdx.x & 31;
    if (warp >= nseg) return;
    int deg = min(cnt[warp], SLOTC);
    int base = warp * SLOTC;
    float a0 = 0.f, a1 = 0.f, a2 = 0.f;
    for (int j = 0; j < deg; j++) {
        int mnode = csl[base + j];
        const float* xp = xin + mnode * 96 + lane;
        a0 += xp[0]; a1 += xp[32]; a2 += xp[64];
    }
    float inv = 1.f / ((float)deg + 1e-9f);
    float* op = outp + warp * 96 + lane;
    op[0] = a0 * inv; op[32] = a1 * inv; op[64] = a2 * inv;
}

__global__ void k_scatadd(float* outp, const int* __restrict__ fp,
                          const float* __restrict__ xin, int nidx) {
    int i = blockIdx.x * blockDim.x + threadIdx.x;
    if (i >= nidx * 96) return;
    int node = i / 96, t = i % 96;
    outp[fp[node] * 96 + t] += xin[i];
}

__global__ void k_mlp(const float* __restrict__ xin, const float* __restrict__ W,
                      float* __restrict__ outp, int n) {
    int i = blockIdx.x * blockDim.x + threadIdx.x;
    if (i >= n * 40) return;
    int node = i / 40, o = i % 40;
    float s = xin[node * 3 + 0] * W[o] + xin[node * 3 + 1] * W[40 + o] +
              xin[node * 3 + 2] * W[80 + o];
    outp[i] = s > 0.f ? s : 0.f;
}

// ---------------- host orchestration ----------------
#define GETSYM(p, s)                  \
    do {                              \
        void* _t;                     \
        cudaGetSymbolAddress(&_t, s); \
        p = (decltype(p))_t;          \
    } while (0)

extern "C" void kernel_launch(void* const* d_in, const int* in_sizes, int n_in,
                              void* d_out, int out_size) {
    const float* pos0 = (const float*)d_in[0];
    const float* v0 = (const float*)d_in[1];
    const float* Wq_first = (const float*)d_in[2];
    const float* Wk_first = (const float*)d_in[3];
    const float* Wv_first = (const float*)d_in[4];
    const float* Ws_first = (const float*)d_in[5];
    const float* Wq_mid = (const float*)d_in[6];
    const float* Wk_mid = (const float*)d_in[7];
    const float* Wv_mid = (const float*)d_in[8];
    const float* Ws_mid = (const float*)d_in[9];
    const float* Wq_last = (const float*)d_in[10];
    const float* Wk_last = (const float*)d_in[11];
    const float* Wv_last = (const float*)d_in[12];
    const float* Ws_last = (const float*)d_in[13];
    const float* wr1 = (const float*)d_in[14];
    const float* wr2 = (const float*)d_in[15];
    const float* scale_mid = (const float*)d_in[16];
    const float* bias_mid = (const float*)d_in[17];
    const float* scale_last = (const float*)d_in[18];
    const float* bias_last = (const float*)d_in[19];
    const float* Wmlp = (const float*)d_in[20];
    const int* src0 = (const int*)d_in[21];
    const int* dst0 = (const int*)d_in[22];
    const int* src1 = (const int*)d_in[23];
    const int* dst1 = (const int*)d_in[24];
    const int* src2 = (const int*)d_in[25];
    const int* dst2 = (const int*)d_in[26];
    const int* fp1 = (const int*)d_in[27];
    const int* fp2 = (const int*)d_in[28];
    const int* cl1 = (const int*)d_in[29];
    const int* cl2 = (const int*)d_in[30];
    float* outp = (float*)d_out;

    float *xA, *xB, *x0s, *x1s, *kt, *vb, *sb, *pos1, *pos2;
    float *rel0, *r0, *rel1, *r1, *rel2, *r2;
    int *cnts, *esl0, *esl1, *esl2, *csl1, *csl2;
    int *gS0, *gS1, *gS2;
    float *gR0, *gR1, *gR2, *gRel0, *gRel1, *gRel2;
    GETSYM(xA, g_xA); GETSYM(xB, g_xB); GETSYM(x0s, g_x0s); GETSYM(x1s, g_x1s);
    GETSYM(kt, g_kt); GETSYM(vb, g_vb); GETSYM(sb, g_sb);
    GETSYM(pos1, g_pos1); GETSYM(pos2, g_pos2);
    GETSYM(rel0, g_rel0); GETSYM(r0, g_r0);
    GETSYM(rel1, g_rel1); GETSYM(r1, g_r1);
    GETSYM(rel2, g_rel2); GETSYM(r2, g_r2);
    GETSYM(cnts, g_cnts);
    GETSYM(esl0, g_esl0); GETSYM(esl1, g_esl1); GETSYM(esl2, g_esl2);
    GETSYM(csl1, g_csl1); GETSYM(csl2, g_csl2);
    GETSYM(gS0, g_gS0); GETSYM(gR0, g_gR0); GETSYM(gRel0, g_gRel0);
    GETSYM(gS1, g_gS1); GETSYM(gR1, g_gR1); GETSYM(gRel1, g_gRel1);
    GETSYM(gS2, g_gS2); GETSYM(gR2, g_gR2); GETSYM(gRel2, g_gRel2);

    int* dE0 = cnts;
    int* dE1 = cnts + N0n;
    int* dE2 = cnts + N0n + N1n;
    int* dC1 = cnts + N0n + N1n + N2n;
    int* dC2 = cnts + N0n + N1n + N2n + N1n;
    const int nCnt = N0n + N1n + N2n + N1n + N2n;

    k_gatherpos<<<(N1n * 3 + 255) / 256, 256>>>(pos1, pos0, fp1, N1n);
    k_gatherpos<<<(N2n * 3 + 255) / 256, 256>>>(pos2, pos1, fp2, N2n);
    k_edgegeo<<<(E0n + 255) / 256, 256>>>(pos0, src0, dst0, rel0, r0, E0n);
    k_edgegeo<<<(E1n + 255) / 256, 256>>>(pos1, src1, dst1, rel1, r1, E1n);
    k_edgegeo<<<(E2n + 255) / 256, 256>>>(pos2, src2, dst2, rel2, r2, E2n);

    k_zeroi<<<(nCnt + 255) / 256, 256>>>(cnts, nCnt);
    k_scat<<<(E0n + 255) / 256, 256>>>(dst0, dE0, esl0, E0n, SLOTE);
    k_scat<<<(E1n + 255) / 256, 256>>>(dst1, dE1, esl1, E1n, SLOTE);
    k_scat<<<(E2n + 255) / 256, 256>>>(dst2, dE2, esl2, E2n, SLOTE);
    k_scat<<<(N0n + 255) / 256, 256>>>(cl1, dC1, csl1, N0n, SLOTC);
    k_scat<<<(N1n + 255) / 256, 256>>>(cl2, dC2, csl2, N1n, SLOTC);
    k_finedge<<<(N0n + 255) / 256, 256>>>(dE0, esl0, src0, rel0, r0, gS0, gR0, gRel0, N0n);
    k_finedge<<<(N1n + 255) / 256, 256>>>(dE1, esl1, src1, rel1, r1, gS1, gR1, gRel1, N1n);
    k_finedge<<<(N2n + 255) / 256, 256>>>(dE2, esl2, src2, rel2, r2, gS2, gR2, gRel2, N2n);
    k_sortc<<<(N1n + 255) / 256, 256>>>(dC1, csl1, N1n);
    k_sortc<<<(N2n + 255) / 256, 256>>>(dC2, csl2, N2n);

    const float scl_mid = 0.10206207261596575f;  // 1/sqrt(96)
    const float scl_last = 0.5773502691896258f;  // 1/sqrt(3)
    auto midW = [&](const float* base, int i) { return base + i * 32 * 32; };
    const int PREP_BLK = 592;

    struct LD {
        int n;
        const int* cnt;
        const int* gS;
        const float *gR, *gRel;
        const float *Wq, *Wk, *Wv, *Ws, *sc, *bi, *w1, *w2;
        const float* xin;
        float* xout;
        float scl;
        int mode;  // 0: Cin=1 Co=32; 1: 32,32; 2: 32,1
    };
    LD L[10];
    L[0] = {N0n, dE0, gS0, gR0, gRel0, Wq_first, Wk_first, Wv_first, Ws_first,
            scale_mid + 0, bias_mid + 0, wr1 + 0, wr2 + 0, v0, xA, scl_mid, 0};
    L[1] = {N0n, dE0, gS0, gR0, gRel0, midW(Wq_mid, 0), midW(Wk_mid, 0), midW(Wv_mid, 0),
            midW(Ws_mid, 0), scale_mid + 32, bias_mid + 32, wr1 + 16, wr2 + 16, xA, x0s,
            scl_mid, 1};
    L[2] = {N1n, dE1, gS1, gR1, gRel1, midW(Wq_mid, 1), midW(Wk_mid, 1), midW(Wv_mid, 1),
            midW(Ws_mid, 1), scale_mid + 64, bias_mid + 64, wr1 + 32, wr2 + 32, xA, xB,
            scl_mid, 1};
    L[3] = {N1n, dE1, gS1, gR1, gRel1, midW(Wq_mid, 2), midW(Wk_mid, 2), midW(Wv_mid, 2),
            midW(Ws_mid, 2), scale_mid + 96, bias_mid + 96, wr1 + 48, wr2 + 48, xB, x1s,
            scl_mid, 1};
    L[4] = {N2n, dE2, gS2, gR2, gRel2, midW(Wq_mid, 3), midW(Wk_mid, 3), midW(Wv_mid, 3),
            midW(Ws_mid, 3), scale_mid + 128, bias_mid + 128, wr1 + 64, wr2 + 64, xA, xB,
            scl_mid, 1};
    L[5] = {N2n, dE2, gS2, gR2, gRel2, midW(Wq_mid, 4), midW(Wk_mid, 4), midW(Wv_mid, 4),
            midW(Ws_mid, 4), scale_mid + 160, bias_mid + 160, wr1 + 80, wr2 + 80, xB, xA,
            scl_mid, 1};
    L[6] = {N1n, dE1, gS1, gR1, gRel1, midW(Wq_mid, 5), midW(Wk_mid, 5), midW(Wv_mid, 5),
            midW(Ws_mid, 5), scale_mid + 192, bias_mid + 192, wr1 + 96, wr2 + 96, xB, xA,
            scl_mid, 1};
    L[7] = {N1n, dE1, gS1, gR1, gRel1, midW(Wq_mid, 6), midW(Wk_mid, 6), midW(Wv_mid, 6),
            midW(Ws_mid, 6), scale_mid + 224, bias_mid + 224, wr1 + 112, wr2 + 112, xA, xB,
            scl_mid, 1};
    L[8] = {N0n, dE0, gS0, gR0, gRel0, midW(Wq_mid, 7), midW(Wk_mid, 7), midW(Wv_mid, 7),
            midW(Ws_mid, 7), scale_mid + 256, bias_mid + 256, wr1 + 128, wr2 + 128, xA, xB,
            scl_mid, 1};
    L[9] = {N0n, dE0, gS0, gR0, gRel0, Wq_last, Wk_last, Wv_last, Ws_last, scale_last,
            bias_last, wr1 + 144, wr2 + 144, xB, xA, scl_last, 2};

    auto run_layer = [&](const LD& d) {
        int want = (d.n + 7) / 8;
        int pblk = PREP_BLK < want ? PREP_BLK : want;
        int ablk = want;
        if (d.mode == 0) {
            k_prep1<<<pblk, 256>>>(d.xin, d.Wq, d.Wk, d.Wv, d.Ws, kt, vb, sb, d.n);
            k_attn<1, 32><<<ablk, 256>>>(d.xin, kt, vb, sb, d.cnt, d.gS, d.gR, d.gRel,
                                         d.w1, d.w2, d.sc, d.bi, d.xout, d.n, d.scl);
        } else if (d.mode == 1) {
            k_prep32<32><<<pblk, 256>>>(d.xin, d.Wq, d.Wk, d.Wv, d.Ws, kt, vb, sb, d.n);
            k_attn<32, 32><<<ablk, 256>>>(d.xin, kt, vb, sb, d.cnt, d.gS, d.gR, d.gRel,
                                          d.w1, d.w2, d.sc, d.bi, d.xout, d.n, d.scl);
        } else {
            k_prep32<1><<<pblk, 256>>>(d.xin, d.Wq, d.Wk, d.Wv, d.Ws, kt, vb, sb, d.n);
            k_attn<32, 1><<<ablk, 256>>>(d.xin, kt, vb, sb, d.cnt, d.gS, d.gR, d.gRel,
                                         d.w1, d.w2, d.sc, d.bi, d.xout, d.n, d.scl);
        }
    };

    run_layer(L[0]);
    run_layer(L[1]);  // -> x0s
    k_segmean<<<(N1n + 7) / 8, 256>>>(x0s, dC1, csl1, xA, N1n);
    run_layer(L[2]);
    run_layer(L[3]);  // -> x1s
    k_segmean<<<(N2n + 7) / 8, 256>>>(x1s, dC2, csl2, xA, N2n);
    run_layer(L[4]);
    run_layer(L[5]);  // -> xA (N2)
    cudaMemcpyAsync(xB, x1s, (size_t)N1n * 96 * sizeof(float), cudaMemcpyDeviceToDevice, 0);
    k_scatadd<<<(N2n * 96 + 255) / 256, 256>>>(xB, fp2, xA, N2n);
    run_layer(L[6]);
    run_layer(L[7]);  // -> xB (N1)
    cudaMemcpyAsync(xA, x0s, (size_t)N0n * 96 * sizeof(float), cudaMemcpyDeviceToDevice, 0);
    k_scatadd<<<(N1n * 96 + 255) / 256, 256>>>(xA, fp1, xB, N1n);
    run_layer(L[8]);
    run_layer(L[9]);  // -> xA [N0,3]
    k_mlp<<<(N0n * 40 + 255) / 256, 256>>>(xA, Wmlp, outp, N0n);
}

// round 5
// speedup vs baseline: 1.4580x; 1.1538x over previous
#include <cuda_runtime.h>

typedef unsigned long long u64;

// ---------------- problem constants ----------------
static const int N0n = 32768;
static const int N1n = 8192;
static const int N2n = 2048;
static const int E0n = N0n * 8;
static const int E1n = N1n * 8;
static const int E2n = N2n * 8;
#define SLOTE 40
#define SLOTC 32

// ---------------- device scratch (static, no allocation) ----------------
__device__ float g_xA[N0n * 96];
__device__ float g_xB[N0n * 96];
__device__ float g_x0s[N0n * 96];
__device__ float g_x1s[N1n * 96];
__device__ float g_kv[N0n * 256];   // [node][lane][8]: 0..2 kt(pre-scaled), 4..6 vb
__device__ float g_sb[N0n * 96];
__device__ float g_pos1[N1n * 3];
__device__ float g_pos2[N2n * 3];
__device__ float4 g_ep0[E0n];       // {bitcast(src), rel.xyz} in edge order
__device__ float4 g_ep1[E1n];
__device__ float4 g_ep2[E2n];
__device__ float4 g_ge0[N0n * SLOTE];  // node-major sorted edge records
__device__ float4 g_ge1[N1n * SLOTE];
__device__ float4 g_ge2[N2n * SLOTE];
__device__ int g_esl0[N0n * SLOTE];
__device__ int g_esl1[N1n * SLOTE];
__device__ int g_esl2[N2n * SLOTE];
__device__ int g_csl1[N1n * SLOTC];
__device__ int g_csl2[N2n * SLOTC];
__device__ int g_cnts[N0n + N1n + N2n + N1n + N2n];

// ---------------- helpers ----------------
__device__ __forceinline__ float warp_sum(float v) {
#pragma unroll
    for (int off = 16; off; off >>= 1) v += __shfl_xor_sync(0xffffffffu, v, off);
    return v;
}
__device__ __forceinline__ u64 pack2(float a, float b) {
    u64 r;
    asm("mov.b64 %0,{%1,%2};" : "=l"(r) : "f"(a), "f"(b));
    return r;
}
__device__ __forceinline__ void fma2(u64& d, u64 a, u64 b) {
    asm("fma.rn.f32x2 %0,%1,%2,%0;" : "+l"(d) : "l"(a), "l"(b));
}
__device__ __forceinline__ float2 unp(u64 v) {
    float2 t;
    asm("mov.b64 {%0,%1},%2;" : "=f"(t.x), "=f"(t.y) : "l"(v));
    return t;
}

// ---------------- build kernels (fused) ----------------
__global__ void k_zeroi(int* p, int n) {
    int i = blockIdx.x * blockDim.x + threadIdx.x;
    if (i < n) p[i] = 0;
}

__global__ void k_scat_all(const int* __restrict__ dst0, const int* __restrict__ dst1,
                           const int* __restrict__ dst2, const int* __restrict__ cl1,
                           const int* __restrict__ cl2, int* dE0, int* dE1, int* dE2,
                           int* dC1, int* dC2, int* esl0, int* esl1, int* esl2, int* csl1,
                           int* csl2) {
    int i = blockIdx.x * blockDim.x + threadIdx.x;
    if (i < E0n) {
        int k = dst0[i];
        int p = atomicAdd(&dE0[k], 1);
        if (p < SLOTE) esl0[k * SLOTE + p] = i;
        return;
    }
    i -= E0n;
    if (i < E1n) {
        int k = dst1[i];
        int p = atomicAdd(&dE1[k], 1);
        if (p < SLOTE) esl1[k * SLOTE + p] = i;
        return;
    }
    i -= E1n;
    if (i < E2n) {
        int k = dst2[i];
        int p = atomicAdd(&dE2[k], 1);
        if (p < SLOTE) esl2[k * SLOTE + p] = i;
        return;
    }
    i -= E2n;
    if (i < N0n) {
        int k = cl1[i];
        int p = atomicAdd(&dC1[k], 1);
        if (p < SLOTC) csl1[k * SLOTC + p] = i;
        return;
    }
    i -= N0n;
    if (i < N1n) {
        int k = cl2[i];
        int p = atomicAdd(&dC2[k], 1);
        if (p < SLOTC) csl2[k * SLOTC + p] = i;
    }
}

__global__ void k_gp_all(const float* __restrict__ pos0, const int* __restrict__ fp1,
                         const int* __restrict__ fp2, float* pos1, float* pos2) {
    int i = blockIdx.x * blockDim.x + threadIdx.x;
    if (i < N1n * 3) {
        int node = i / 3, c = i % 3;
        pos1[i] = pos0[fp1[node] * 3 + c];
        return;
    }
    i -= N1n * 3;
    if (i < N2n * 3) {
        int node = i / 3, c = i % 3;
        pos2[i] = pos0[fp1[fp2[node]] * 3 + c];
    }
}

__device__ __forceinline__ void eg_one(const float* pos, int s, int d, float4* ep, int e) {
    float a = pos[d * 3 + 0] - pos[s * 3 + 0];
    float b = pos[d * 3 + 1] - pos[s * 3 + 1];
    float c = pos[d * 3 + 2] - pos[s * 3 + 2];
    ep[e] = make_float4(__int_as_float(s), a, b, c);
}

__global__ void k_eg_all(const float* __restrict__ pos0, const float* __restrict__ pos1,
                         const float* __restrict__ pos2, const int* __restrict__ s0,
                         const int* __restrict__ d0, const int* __restrict__ s1,
                         const int* __restrict__ d1, const int* __restrict__ s2,
                         const int* __restrict__ d2, float4* ep0, float4* ep1, float4* ep2) {
    int i = blockIdx.x * blockDim.x + threadIdx.x;
    if (i < E0n) { eg_one(pos0, s0[i], d0[i], ep0, i); return; }
    i -= E0n;
    if (i < E1n) { eg_one(pos1, s1[i], d1[i], ep1, i); return; }
    i -= E1n;
    if (i < E2n) { eg_one(pos2, s2[i], d2[i], ep2, i); }
}

__device__ __forceinline__ void finedge_one(int* slot, const int* cnt, const float4* ep,
                                            float4* ge, int node) {
    int deg = min(cnt[node], SLOTE);
    int base = node * SLOTE;
    for (int a = 1; a < deg; a++) {
        int v = slot[base + a];
        int b = a - 1;
        while (b >= 0 && slot[base + b] > v) { slot[base + b + 1] = slot[base + b]; b--; }
        slot[base + b + 1] = v;
    }
    for (int j = 0; j < deg; j++) ge[base + j] = ep[slot[base + j]];
}

__device__ __forceinline__ void sortc_one(int* slot, const int* cnt, int node) {
    int deg = min(cnt[node], SLOTC);
    int base = node * SLOTC;
    for (int a = 1; a < deg; a++) {
        int v = slot[base + a];
        int b = a - 1;
        while (b >= 0 && slot[base + b] > v) { slot[base + b + 1] = slot[base + b]; b--; }
        slot[base + b + 1] = v;
    }
}

__global__ void k_finsort_all(int* esl0, int* esl1, int* esl2, int* csl1, int* csl2,
                              const int* __restrict__ dE0, const int* __restrict__ dE1,
                              const int* __restrict__ dE2, const int* __restrict__ dC1,
                              const int* __restrict__ dC2, const float4* __restrict__ ep0,
                              const float4* __restrict__ ep1, const float4* __restrict__ ep2,
                              float4* ge0, float4* ge1, float4* ge2) {
    int i = blockIdx.x * blockDim.x + threadIdx.x;
    if (i < N0n) { finedge_one(esl0, dE0, ep0, ge0, i); return; }
    i -= N0n;
    if (i < N1n) { finedge_one(esl1, dE1, ep1, ge1, i); return; }
    i -= N1n;
    if (i < N2n) { finedge_one(esl2, dE2, ep2, ge2, i); return; }
    i -= N2n;
    if (i < N1n) { sortc_one(csl1, dC1, i); return; }
    i -= N1n;
    if (i < N2n) { sortc_one(csl2, dC2, i); }
}

// ---------------- layer 0: fused attention (Cin=1 -> Co=32), no prep ----------------
__global__ __launch_bounds__(256) void k_attn0(
    const float* __restrict__ x, const float4* __restrict__ ge, const int* __restrict__ cnt,
    const float* __restrict__ Wq, const float* __restrict__ Wk, const float* __restrict__ Wv,
    const float* __restrict__ Ws, const float* __restrict__ w1, const float* __restrict__ w2,
    const float* __restrict__ scale, const float* __restrict__ bias, float* __restrict__ outp,
    int n, float scl) {
    int warp = threadIdx.x >> 5, lane = threadIdx.x & 31;
    int node = blockIdx.x * 8 + warp;
    if (node >= n) return;
    float Gs = warp_sum(Wq[lane] * Wk[lane]) * scl;
    float wv = Wv[lane], ws = Ws[lane];
    float rw1 = (lane < 16) ? w1[lane] : 0.f;
    float rw2 = (lane < 16) ? w2[lane] : 0.f;
    float sc = scale[lane], bi = bias[lane];
    float xd0 = x[node * 3 + 0], xd1 = x[node * 3 + 1], xd2 = x[node * 3 + 2];
    int deg = min(cnt[node], SLOTE);
    int base = node * SLOTE;
    float z = 0.f, a0 = 0.f, a1 = 0.f, a2 = 0.f;
    int j = 0;
    for (; j + 2 <= deg; j += 2) {
        float4 e0 = ge[base + j];
        float4 e1 = ge[base + j + 1];
        int s0 = __float_as_int(e0.x), s1 = __float_as_int(e1.x);
        float xs00 = x[s0 * 3 + 0], xs01 = x[s0 * 3 + 1], xs02 = x[s0 * 3 + 2];
        float xs10 = x[s1 * 3 + 0], xs11 = x[s1 * 3 + 1], xs12 = x[s1 * 3 + 2];
        float rr0 = sqrtf(e0.y * e0.y + e0.z * e0.z + e0.w * e0.w + 1e-12f);
        float rr1 = sqrtf(e1.y * e1.y + e1.z * e1.z + e1.w * e1.w + 1e-12f);
        float p0 = fmaxf(rr0 * rw1, 0.f) * rw2;
        float p1 = fmaxf(rr1 * rw1, 0.f) * rw2;
#pragma unroll
        for (int off = 16; off; off >>= 1) {
            p0 += __shfl_xor_sync(0xffffffffu, p0, off);
            p1 += __shfl_xor_sync(0xffffffffu, p1, off);
        }
        float w0 = __expf(Gs * (xd0 * xs00 + xd1 * xs01 + xd2 * xs02) + p0);
        float w1f = __expf(Gs * (xd0 * xs10 + xd1 * xs11 + xd2 * xs12) + p1);
        z += w0 + w1f;
        a0 += w0 * (xs00 * wv + e0.y) + w1f * (xs10 * wv + e1.y);
        a1 += w0 * (xs01 * wv + e0.z) + w1f * (xs11 * wv + e1.z);
        a2 += w0 * (xs02 * wv + e0.w) + w1f * (xs12 * wv + e1.w);
    }
    if (j < deg) {
        float4 e0 = ge[base + j];
        int s0 = __float_as_int(e0.x);
        float xs00 = x[s0 * 3 + 0], xs01 = x[s0 * 3 + 1], xs02 = x[s0 * 3 + 2];
        float rr0 = sqrtf(e0.y * e0.y + e0.z * e0.z + e0.w * e0.w + 1e-12f);
        float p0 = warp_sum(fmaxf(rr0 * rw1, 0.f) * rw2);
        float w0 = __expf(Gs * (xd0 * xs00 + xd1 * xs01 + xd2 * xs02) + p0);
        z += w0;
        a0 += w0 * (xs00 * wv + e0.y);
        a1 += w0 * (xs01 * wv + e0.z);
        a2 += w0 * (xs02 * wv + e0.w);
    }
    float invz = 1.f / (z + 1e-9f);
    a0 = a0 * invz + xd0 * ws;
    a1 = a1 * invz + xd1 * ws;
    a2 = a2 * invz + xd2 * ws;
    float nrm = sqrtf(a0 * a0 + a1 * a1 + a2 * a2 + 1e-12f);
    float t = fmaxf(sc * nrm + bi, 0.f);
    float f = t / nrm;
    float* op = outp + node * 96 + lane;
    op[0] = a0 * f;
    op[32] = a1 * f;
    op[64] = a2 * f;
}

// ---------------- prep for Cin=32 layers: kv (kt pre-scaled) + sb ----------------
template <int Co>
__global__ __launch_bounds__(256) void k_prep32(const float* __restrict__ x,
                                                const float* __restrict__ Wq,
                                                const float* __restrict__ Wk,
                                                const float* __restrict__ Wv,
                                                const float* __restrict__ Ws,
                                                float* __restrict__ kv, float* __restrict__ sb,
                                                int n, float scl) {
    const int Cin = 32;
    const int H = 16;
    int tid = threadIdx.x;
    int warp = tid >> 5, lane = tid & 31;
    __shared__ u64 sGp[H * Cin];
    __shared__ u64 sWvp[H * Co];
    __shared__ u64 sWsp[H * Co];
    __shared__ u64 sxp[8][3 * H];
    for (int i = tid; i < H * Cin; i += 256) {
        int c2 = i / Cin, o = i % Cin;
        float g0 = 0.f, g1 = 0.f;
        for (int j = 0; j < Co; j++) {
            float wq = Wq[o * Co + j];
            g0 += wq * Wk[(2 * c2) * Co + j];
            g1 += wq * Wk[(2 * c2 + 1) * Co + j];
        }
        sGp[i] = pack2(g0 * scl, g1 * scl);
    }
    for (int i = tid; i < H * Co; i += 256) {
        int c2 = i / Co, o = i % Co;
        sWvp[i] = pack2(Wv[(2 * c2) * Co + o], Wv[(2 * c2 + 1) * Co + o]);
        sWsp[i] = pack2(Ws[(2 * c2) * Co + o], Ws[(2 * c2 + 1) * Co + o]);
    }
    __syncthreads();
    for (int node = blockIdx.x * 8 + warp; node < n; node += gridDim.x * 8) {
        const float2* xr = (const float2*)(x + node * 96);
        for (int i = lane; i < 3 * H; i += 32) {
            float2 t = xr[i];
            sxp[warp][i] = pack2(t.x, t.y);
        }
        __syncwarp();
        u64 k0 = 0, k1 = 0, k2 = 0, v0a = 0, v1a = 0, v2a = 0, s0a = 0, s1a = 0, s2a = 0;
#pragma unroll
        for (int c2 = 0; c2 < H; c2++) {
            u64 px0 = sxp[warp][c2];
            u64 px1 = sxp[warp][H + c2];
            u64 px2 = sxp[warp][2 * H + c2];
            {
                u64 g = sGp[c2 * Cin + lane];
                fma2(k0, px0, g);
                fma2(k1, px1, g);
                fma2(k2, px2, g);
            }
            if (Co == 32 || lane < Co) {
                int li = (Co == 32) ? lane : 0;
                u64 wv = sWvp[c2 * Co + li];
                u64 ws = sWsp[c2 * Co + li];
                fma2(v0a, px0, wv);
                fma2(v1a, px1, wv);
                fma2(v2a, px2, wv);
                fma2(s0a, px0, ws);
                fma2(s1a, px1, ws);
                fma2(s2a, px2, ws);
            }
        }
        {
            float2 a = unp(k0), b = unp(k1), c = unp(k2);
            float4 ktv = make_float4(a.x + a.y, b.x + b.y, c.x + c.y, 0.f);
            *(float4*)(kv + (size_t)node * 256 + lane * 8) = ktv;
        }
        if (lane < Co) {
            float2 a = unp(v0a), b = unp(v1a), c = unp(v2a);
            float4 vbv = make_float4(a.x + a.y, b.x + b.y, c.x + c.y, 0.f);
            *(float4*)(kv + (size_t)node * 256 + lane * 8 + 4) = vbv;
            a = unp(s0a);
            b = unp(s1a);
            c = unp(s2a);
            float* sp = sb + node * 3 * Co + lane;
            sp[0] = a.x + a.y;
            sp[Co] = b.x + b.y;
            sp[2 * Co] = c.x + c.y;
        }
        __syncwarp();
    }
}

// ---------------- attention Cin=32 (no-max softmax, float4 gathers, x2 unroll) ----------------
template <int Co>
__global__ __launch_bounds__(256) void k_attn32(
    const float* __restrict__ x, const float* __restrict__ kv, const float* __restrict__ sb,
    const float4* __restrict__ ge, const int* __restrict__ cnt, const float* __restrict__ w1,
    const float* __restrict__ w2, const float* __restrict__ scale,
    const float* __restrict__ bias, float* __restrict__ outp, int n) {
    int warp = threadIdx.x >> 5, lane = threadIdx.x & 31;
    int node = blockIdx.x * 8 + warp;
    if (node >= n) return;
    float rw1 = (lane < 16) ? w1[lane] : 0.f;
    float rw2 = (lane < 16) ? w2[lane] : 0.f;
    float sc = (lane < Co) ? scale[lane] : 0.f;
    float bi = (lane < Co) ? bias[lane] : 0.f;
    int deg = min(cnt[node], SLOTE);
    int base = node * SLOTE;
    const float* xp = x + node * 96 + lane;
    float xd0 = xp[0], xd1 = xp[32], xd2 = xp[64];
    float z = 0.f, a0 = 0.f, a1 = 0.f, a2 = 0.f;
    int j = 0;
    for (; j + 2 <= deg; j += 2) {
        float4 e0 = ge[base + j];
        float4 e1 = ge[base + j + 1];
        int s0 = __float_as_int(e0.x), s1 = __float_as_int(e1.x);
        const float4* kvp0 = (const float4*)(kv + (size_t)s0 * 256) + (lane << 1);
        const float4* kvp1 = (const float4*)(kv + (size_t)s1 * 256) + (lane << 1);
        float4 k40 = kvp0[0];
        float4 k41 = kvp1[0];
        float4 v40 = kvp0[1];
        float4 v41 = kvp1[1];
        float rr0 = sqrtf(e0.y * e0.y + e0.z * e0.z + e0.w * e0.w + 1e-12f);
        float rr1 = sqrtf(e1.y * e1.y + e1.z * e1.z + e1.w * e1.w + 1e-12f);
        float p0 = xd0 * k40.x + xd1 * k40.y + xd2 * k40.z + fmaxf(rr0 * rw1, 0.f) * rw2;
        float p1 = xd0 * k41.x + xd1 * k41.y + xd2 * k41.z + fmaxf(rr1 * rw1, 0.f) * rw2;
#pragma unroll
        for (int off = 16; off; off >>= 1) {
            p0 += __shfl_xor_sync(0xffffffffu, p0, off);
            p1 += __shfl_xor_sync(0xffffffffu, p1, off);
        }
        float w0 = __expf(p0);
        float w1f = __expf(p1);
        z += w0 + w1f;
        if (Co == 32) {
            a0 += w0 * (v40.x + e0.y) + w1f * (v41.x + e1.y);
            a1 += w0 * (v40.y + e0.z) + w1f * (v41.y + e1.z);
            a2 += w0 * (v40.z + e0.w) + w1f * (v41.z + e1.w);
        } else if (lane == 0) {
            a0 += w0 * (v40.x + e0.y) + w1f * (v41.x + e1.y);
            a1 += w0 * (v40.y + e0.z) + w1f * (v41.y + e1.z);
            a2 += w0 * (v40.z + e0.w) + w1f * (v41.z + e1.w);
        }
    }
    if (j < deg) {
        float4 e0 = ge[base + j];
        int s0 = __float_as_int(e0.x);
        const float4* kvp0 = (const float4*)(kv + (size_t)s0 * 256) + (lane << 1);
        float4 k40 = kvp0[0];
        float4 v40 = kvp0[1];
        float rr0 = sqrtf(e0.y * e0.y + e0.z * e0.z + e0.w * e0.w + 1e-12f);
        float p0 = warp_sum(xd0 * k40.x + xd1 * k40.y + xd2 * k40.z +
                            fmaxf(rr0 * rw1, 0.f) * rw2);
        float w0 = __expf(p0);
        z += w0;
        if (Co == 32) {
            a0 += w0 * (v40.x + e0.y);
            a1 += w0 * (v40.y + e0.z);
            a2 += w0 * (v40.z + e0.w);
        } else if (lane == 0) {
            a0 += w0 * (v40.x + e0.y);
            a1 += w0 * (v40.y + e0.z);
            a2 += w0 * (v40.z + e0.w);
        }
    }
    float invz = 1.f / (z + 1e-9f);
    if (lane < Co) {
        const float* sp = sb + node * 3 * Co + lane;
        a0 = a0 * invz + sp[0];
        a1 = a1 * invz + sp[Co];
        a2 = a2 * invz + sp[2 * Co];
        float nrm = sqrtf(a0 * a0 + a1 * a1 + a2 * a2 + 1e-12f);
        float t = fmaxf(sc * nrm + bi, 0.f);
        float f = t / nrm;
        float* op = outp + node * 3 * Co + lane;
        op[0] = a0 * f;
        op[Co] = a1 * f;
        op[2 * Co] = a2 * f;
    }
}

// ---------------- pooling / upsample / head ----------------
__global__ void k_segmean(const float* __restrict__ xin, const int* __restrict__ cnt,
                          const int* __restrict__ csl, float* __restrict__ outp, int nseg) {
    int warp = (blockIdx.x * blockDim.x + threadIdx.x) >> 5;
    int lane = threadIdx.x & 31;
    if (warp >= nseg) return;
    int deg = min(cnt[warp], SLOTC);
    int base = warp * SLOTC;
    float a0 = 0.f, a1 = 0.f, a2 = 0.f;
    for (int j = 0; j < deg; j++) {
        int mnode = csl[base + j];
        const float* xp = xin + mnode * 96 + lane;
        a0 += xp[0];
        a1 += xp[32];
        a2 += xp[64];
    }
    float inv = 1.f / ((float)deg + 1e-9f);
    float* op = outp + warp * 96 + lane;
    op[0] = a0 * inv;
    op[32] = a1 * inv;
    op[64] = a2 * inv;
}

__global__ void k_scatadd(float* outp, const int* __restrict__ fp,
                          const float* __restrict__ xin, int nidx) {
    int i = blockIdx.x * blockDim.x + threadIdx.x;
    if (i >= nidx * 96) return;
    int node = i / 96, t = i % 96;
    outp[fp[node] * 96 + t] += xin[i];
}

__global__ void k_mlp(const float* __restrict__ xin, const float* __restrict__ W,
                      float* __restrict__ outp, int n) {
    int i = blockIdx.x * blockDim.x + threadIdx.x;
    if (i >= n * 40) return;
    int node = i / 40, o = i % 40;
    float s = xin[node * 3 + 0] * W[o] + xin[node * 3 + 1] * W[40 + o] +
              xin[node * 3 + 2] * W[80 + o];
    outp[i] = s > 0.f ? s : 0.f;
}

// ---------------- host orchestration ----------------
#define GETSYM(p, s)                  \
    do {                              \
        void* _t;                     \
        cudaGetSymbolAddress(&_t, s); \
        p = (decltype(p))_t;          \
    } while (0)

extern "C" void kernel_launch(void* const* d_in, const int* in_sizes, int n_in,
                              void* d_out, int out_size) {
    const float* pos0 = (const float*)d_in[0];
    const float* v0 = (const float*)d_in[1];
    const float* Wq_first = (const float*)d_in[2];
    const float* Wk_first = (const float*)d_in[3];
    const float* Wv_first = (const float*)d_in[4];
    const float* Ws_first = (const float*)d_in[5];
    const float* Wq_mid = (const float*)d_in[6];
    const float* Wk_mid = (const float*)d_in[7];
    const float* Wv_mid = (const float*)d_in[8];
    const float* Ws_mid = (const float*)d_in[9];
    const float* Wq_last = (const float*)d_in[10];
    const float* Wk_last = (const float*)d_in[11];
    const float* Wv_last = (const float*)d_in[12];
    const float* Ws_last = (const float*)d_in[13];
    const float* wr1 = (const float*)d_in[14];
    const float* wr2 = (const float*)d_in[15];
    const float* scale_mid = (const float*)d_in[16];
    const float* bias_mid = (const float*)d_in[17];
    const float* scale_last = (const float*)d_in[18];
    const float* bias_last = (const float*)d_in[19];
    const float* Wmlp = (const float*)d_in[20];
    const int* src0 = (const int*)d_in[21];
    const int* dst0 = (const int*)d_in[22];
    const int* src1 = (const int*)d_in[23];
    const int* dst1 = (const int*)d_in[24];
    const int* src2 = (const int*)d_in[25];
    const int* dst2 = (const int*)d_in[26];
    const int* fp1 = (const int*)d_in[27];
    const int* fp2 = (const int*)d_in[28];
    const int* cl1 = (const int*)d_in[29];
    const int* cl2 = (const int*)d_in[30];
    float* outp = (float*)d_out;

    float *xA, *xB, *x0s, *x1s, *kv, *sb, *pos1, *pos2;
    float4 *ep0, *ep1, *ep2, *ge0, *ge1, *ge2;
    int *cnts, *esl0, *esl1, *esl2, *csl1, *csl2;
    GETSYM(xA, g_xA); GETSYM(xB, g_xB); GETSYM(x0s, g_x0s); GETSYM(x1s, g_x1s);
    GETSYM(kv, g_kv); GETSYM(sb, g_sb);
    GETSYM(pos1, g_pos1); GETSYM(pos2, g_pos2);
    GETSYM(ep0, g_ep0); GETSYM(ep1, g_ep1); GETSYM(ep2, g_ep2);
    GETSYM(ge0, g_ge0); GETSYM(ge1, g_ge1); GETSYM(ge2, g_ge2);
    GETSYM(esl0, g_esl0); GETSYM(esl1, g_esl1); GETSYM(esl2, g_esl2);
    GETSYM(csl1, g_csl1); GETSYM(csl2, g_csl2);
    GETSYM(cnts, g_cnts);

    int* dE0 = cnts;
    int* dE1 = cnts + N0n;
    int* dE2 = cnts + N0n + N1n;
    int* dC1 = cnts + N0n + N1n + N2n;
    int* dC2 = cnts + N0n + N1n + N2n + N1n;
    const int nCnt = N0n + N1n + N2n + N1n + N2n;

    const float scl_mid = 0.10206207261596575f;  // 1/sqrt(96)
    const float scl_last = 0.5773502691896258f;  // 1/sqrt(3)
    auto midW = [&](const float* base, int i) { return base + i * 32 * 32; };
    const int PREP_BLK = 592;

    // ---- build (launches 0..4) ----
    k_zeroi<<<(nCnt + 255) / 256, 256>>>(cnts, nCnt);
    {
        int tot = E0n + E1n + E2n + N0n + N1n;
        k_scat_all<<<(tot + 255) / 256, 256>>>(dst0, dst1, dst2, cl1, cl2, dE0, dE1, dE2,
                                               dC1, dC2, esl0, esl1, esl2, csl1, csl2);
    }
    k_gp_all<<<((N1n + N2n) * 3 + 255) / 256, 256>>>(pos0, fp1, fp2, pos1, pos2);
    {
        int tot = E0n + E1n + E2n;
        k_eg_all<<<(tot + 255) / 256, 256>>>(pos0, pos1, pos2, src0, dst0, src1, dst1, src2,
                                             dst2, ep0, ep1, ep2);
    }
    {
        int tot = N0n + N1n + N2n + N1n + N2n;
        k_finsort_all<<<(tot + 255) / 256, 256>>>(esl0, esl1, esl2, csl1, csl2, dE0, dE1,
                                                  dE2, dC1, dC2, ep0, ep1, ep2, ge0, ge1,
                                                  ge2);
    }

    // ---- layer 0 (fused, launch 5) ----
    k_attn0<<<(N0n + 7) / 8, 256>>>(v0, ge0, dE0, Wq_first, Wk_first, Wv_first, Ws_first,
                                    wr1 + 0, wr2 + 0, scale_mid + 0, bias_mid + 0, xA, N0n,
                                    scl_mid);

    struct LD {
        int n;
        const int* cnt;
        const float4* ge;
        const float *Wq, *Wk, *Wv, *Ws, *sc, *bi, *w1, *w2;
        const float* xin;
        float* xout;
        float scl;
        int co;  // 32 or 1
    };
    LD L[10];
    L[1] = {N0n, dE0, ge0, midW(Wq_mid, 0), midW(Wk_mid, 0), midW(Wv_mid, 0),
            midW(Ws_mid, 0), scale_mid + 32, bias_mid + 32, wr1 + 16, wr2 + 16, xA, x0s,
            scl_mid, 32};
    L[2] = {N1n, dE1, ge1, midW(Wq_mid, 1), midW(Wk_mid, 1), midW(Wv_mid, 1),
            midW(Ws_mid, 1), scale_mid + 64, bias_mid + 64, wr1 + 32, wr2 + 32, xA, xB,
            scl_mid, 32};
    L[3] = {N1n, dE1, ge1, midW(Wq_mid, 2), midW(Wk_mid, 2), midW(Wv_mid, 2),
            midW(Ws_mid, 2), scale_mid + 96, bias_mid + 96, wr1 + 48, wr2 + 48, xB, x1s,
            scl_mid, 32};
    L[4] = {N2n, dE2, ge2, midW(Wq_mid, 3), midW(Wk_mid, 3), midW(Wv_mid, 3),
            midW(Ws_mid, 3), scale_mid + 128, bias_mid + 128, wr1 + 64, wr2 + 64, xA, xB,
            scl_mid, 32};
    L[5] = {N2n, dE2, ge2, midW(Wq_mid, 4), midW(Wk_mid, 4), midW(Wv_mid, 4),
            midW(Ws_mid, 4), scale_mid + 160, bias_mid + 160, wr1 + 80, wr2 + 80, xB, xA,
            scl_mid, 32};
    L[6] = {N1n, dE1, ge1, midW(Wq_mid, 5), midW(Wk_mid, 5), midW(Wv_mid, 5),
            midW(Ws_mid, 5), scale_mid + 192, bias_mid + 192, wr1 + 96, wr2 + 96, xB, xA,
            scl_mid, 32};
    L[7] = {N1n, dE1, ge1, midW(Wq_mid, 6), midW(Wk_mid, 6), midW(Wv_mid, 6),
            midW(Ws_mid, 6), scale_mid + 224, bias_mid + 224, wr1 + 112, wr2 + 112, xA, xB,
            scl_mid, 32};
    L[8] = {N0n, dE0, ge0, midW(Wq_mid, 7), midW(Wk_mid, 7), midW(Wv_mid, 7),
            midW(Ws_mid, 7), scale_mid + 256, bias_mid + 256, wr1 + 128, wr2 + 128, xA, xB,
            scl_mid, 32};
    L[9] = {N0n, dE0, ge0, Wq_last, Wk_last, Wv_last, Ws_last, scale_last, bias_last,
            wr1 + 144, wr2 + 144, xB, xA, scl_last, 1};

    auto run_layer = [&](const LD& d) {
        int want = (d.n + 7) / 8;
        int pblk = PREP_BLK < want ? PREP_BLK : want;
        if (d.co == 32) {
            k_prep32<32><<<pblk, 256>>>(d.xin, d.Wq, d.Wk, d.Wv, d.Ws, kv, sb, d.n, d.scl);
            k_attn32<32><<<want, 256>>>(d.xin, kv, sb, d.ge, d.cnt, d.w1, d.w2, d.sc, d.bi,
                                        d.xout, d.n);
        } else {
            k_prep32<1><<<pblk, 256>>>(d.xin, d.Wq, d.Wk, d.Wv, d.Ws, kv, sb, d.n, d.scl);
            k_attn32<1><<<want, 256>>>(d.xin, kv, sb, d.ge, d.cnt, d.w1, d.w2, d.sc, d.bi,
                                       d.xout, d.n);
        }
    };

    run_layer(L[1]);  // -> x0s
    k_segmean<<<(N1n + 7) / 8, 256>>>(x0s, dC1, csl1, xA, N1n);
    run_layer(L[2]);
    run_layer(L[3]);  // -> x1s
    k_segmean<<<(N2n + 7) / 8, 256>>>(x1s, dC2, csl2, xA, N2n);
    run_layer(L[4]);
    run_layer(L[5]);  // -> xA (N2)
    cudaMemcpyAsync(xB, x1s, (size_t)N1n * 96 * sizeof(float), cudaMemcpyDeviceToDevice, 0);
    k_scatadd<<<(N2n * 96 + 255) / 256, 256>>>(xB, fp2, xA, N2n);
    run_layer(L[6]);
    run_layer(L[7]);  // -> xB (N1)
    cudaMemcpyAsync(xA, x0s, (size_t)N0n * 96 * sizeof(float), cudaMemcpyDeviceToDevice, 0);
    k_scatadd<<<(N1n * 96 + 255) / 256, 256>>>(xA, fp1, xB, N1n);
    run_layer(L[8]);
    run_layer(L[9]);  // -> xA [N0,3]
    k_mlp<<<(N0n * 40 + 255) / 256, 256>>>(xA, Wmlp, outp, N0n);
}